// round 14
// baseline (speedup 1.0000x reference)
#include <cuda_runtime.h>
#include <cuda_bf16.h>

#define FULL 0xffffffffu

static __device__ __forceinline__ unsigned long long pk2(float lo, float hi) {
    unsigned long long r;
    asm("mov.b64 %0, {%1,%2};" : "=l"(r) : "f"(lo), "f"(hi));
    return r;
}
static __device__ __forceinline__ void upk2(unsigned long long v, float& lo, float& hi) {
    asm("mov.b64 {%0,%1}, %2;" : "=f"(lo), "=f"(hi) : "l"(v));
}
static __device__ __forceinline__ unsigned long long fma2(unsigned long long a,
                                                          unsigned long long b,
                                                          unsigned long long c) {
    unsigned long long d;
    asm("fma.rn.f32x2 %0,%1,%2,%3;" : "=l"(d) : "l"(a), "l"(b), "l"(c));
    return d;
}
static __device__ __forceinline__ unsigned long long add2(unsigned long long a,
                                                           unsigned long long b) {
    unsigned long long d;
    asm("add.rn.f32x2 %0,%1,%2;" : "=l"(d) : "l"(a), "l"(b));
    return d;
}
static __device__ __forceinline__ unsigned long long mul2(unsigned long long a,
                                                           unsigned long long b) {
    unsigned long long d;
    asm("mul.rn.f32x2 %0,%1,%2;" : "=l"(d) : "l"(a), "l"(b));
    return d;
}

static constexpr int Bb = 256;
static constexpr int Tt = 2048;
static constexpr int Dd = 64;
static constexpr int NSEG = 8;
static constexpr int SEGT = Tt / NSEG;

__device__ float s12p[Bb][NSEG];
__device__ int   Lg[Bb];

// ============================================================================
// Pass 1a: valid length per batch.
// ============================================================================
__global__ __launch_bounds__(256) void len_kernel(const int* __restrict__ mask) {
    const int b = blockIdx.x, tid = threadIdx.x, w = tid >> 5, l = tid & 31;
    __shared__ int red[8];
    const int4* m4 = reinterpret_cast<const int4*>(mask + (size_t)b * Tt);
    int4 a = m4[tid], c = m4[256 + tid];
    int s = a.x + a.y + a.z + a.w + c.x + c.y + c.z + c.w;
#pragma unroll
    for (int o = 16; o > 0; o >>= 1) s += __shfl_xor_sync(FULL, s, o);
    if (l == 0) red[w] = s;
    __syncthreads();
    if (tid == 0) {
        int tot = 0;
#pragma unroll
        for (int j = 0; j < 8; j++) tot += red[j];
        Lg[b] = Tt - tot;
    }
}

// ============================================================================
// Pass 1b: emission + transition score partial for one (batch, segment).
// ============================================================================
__global__ __launch_bounds__(256) void score_kernel(
    const float* __restrict__ p,
    const int*   __restrict__ y,
    const float* __restrict__ trans)
{
    const int blk = blockIdx.x;
    const int b = blk >> 3, seg = blk & (NSEG - 1);
    const int tid = threadIdx.x, w = tid >> 5, l = tid & 31;
    const int t0 = seg * SEGT;

    __shared__ short lab[SEGT + 1];
    __shared__ float red[8];

    const int2* yB = reinterpret_cast<const int2*>(y + (size_t)b * Tt * Dd);
#pragma unroll 4
    for (int i = w; i <= SEGT; i += 8) {
        int t = t0 + i;
        if (t < Tt) {
            int2 yv = yB[t * 32 + l];
            unsigned bx = __ballot_sync(FULL, yv.x != 0);
            unsigned by = __ballot_sync(FULL, yv.y != 0);
            if (l == 0)
                lab[i] = bx ? (short)(2 * (__ffs(bx) - 1))
                            : (short)(2 * (__ffs(by) - 1) + 1);
        }
    }
    __syncthreads();

    const int L = Lg[b];
    const int t = t0 + tid;
    const int lt = lab[tid];
    float acc = 0.f;
    if (t < L)     acc += __ldg(&p[(size_t)b * Tt * Dd + (size_t)t * Dd + lt]);
    if (t + 1 < L) acc += __ldg(&trans[lt * Dd + lab[tid + 1]]);

#pragma unroll
    for (int o = 16; o > 0; o >>= 1) acc += __shfl_xor_sync(FULL, acc, o);
    if (l == 0) red[w] = acc;
    __syncthreads();
    if (tid == 0) {
        float tot = 0.f;
#pragma unroll
        for (int j = 0; j < 8; j++) tot += red[j];
        s12p[b][seg] = tot;
    }
}

// ============================================================================
// Pass 2: forward recurrence. ONE WARP PER BATCH (solo-warp champion shape),
// restructured: outer loop over 8-step chunks with a fully-unrolled,
// BRANCH-FREE inner body, so independent emission work (pt LDS, MUFU exps,
// packing) of step t+1 overlaps step t's 128-cycle fma stretch. Chunk
// staging commit/prefetch sits once per 8 steps, off the hot path.
// Linear domain with power-of-two renormalization (exponent of v[0] read
// directly from smem, one stale step, exact power-of-2 scaling).
// ============================================================================
static constexpr int CH  = 8;
static constexpr int NCH = Tt / CH;

__global__ __launch_bounds__(64) void crf_forward_kernel(
    const float* __restrict__ p,       // [B,T,D]
    const float* __restrict__ trans,   // [D,D]
    float*       __restrict__ out)     // [B]
{
    const int w = threadIdx.x >> 5;
    const int l = threadIdx.x & 31;
    const int b = blockIdx.x * 2 + w;

    __shared__ __align__(16) unsigned long long sh[2][Dd];  // [warp][col] {v,v}
    __shared__ __align__(16) float sp[2][2][CH][Dd];        // [warp][buf][t][d]

    const int L = Lg[b];

    // expT: all 64 rows, cols (2l,2l+1), packed in 64 u64 regs
    unsigned long long eT[64];
#pragma unroll
    for (int j = 0; j < 64; j++) {
        float2 tv = reinterpret_cast<const float2*>(trans)[j * 32 + l];
        eT[j] = pk2(__expf(tv.x), __expf(tv.y));
    }

    const float4* p4 = reinterpret_cast<const float4*>(p + (size_t)b * Tt * Dd);

    // stage chunks 0,1; prefetch chunk 2 (4 float4/lane each)
    float4 prf[4];
#pragma unroll
    for (int j = 0; j < 4; j++) {
        reinterpret_cast<float4*>(sp[w][0])[j * 32 + l] = p4[j * 32 + l];
        reinterpret_cast<float4*>(sp[w][1])[j * 32 + l] = p4[128 + j * 32 + l];
        prf[j] = p4[256 + j * 32 + l];
    }
    __syncwarp();

    // ---- t = 0 init ----
    float2 p0 = *reinterpret_cast<const float2*>(&sp[w][0][0][2 * l]);
    float vx = __expf(p0.x);
    float vy = __expf(p0.y);
    int ktot = 0;
    {
        ulonglong2 stv;
        stv.x = pk2(vx, vx);
        stv.y = pk2(vy, vy);
        *reinterpret_cast<ulonglong2*>(&sh[w][2 * l]) = stv;
    }
    __syncwarp();

    const ulonglong2* shv = reinterpret_cast<const ulonglong2*>(sh[w]);
    const unsigned long long* shs = sh[w];

// One forward step reading emission row ROW (float[64]).
// ebits reads PREVIOUS state's v[0] (program order before this step's STS;
// same-array aliasing keeps the compiler from reordering). Memory clobber at
// the end orders consecutive steps.
#define CRF_STEP(ROW) do {                                                    \
    const float2 pt_ = *reinterpret_cast<const float2*>((ROW) + 2 * l);       \
    const unsigned eb_ = *reinterpret_cast<const unsigned*>(shs);             \
    const int k_ = (int)((eb_ >> 23) & 255) - 127;                            \
    ktot += k_;                                                               \
    const float sc_ = __uint_as_float((unsigned)(127 - k_) << 23);            \
    const unsigned long long ep_ = pk2(__expf(pt_.x) * sc_,                   \
                                       __expf(pt_.y) * sc_);                  \
    unsigned long long a0_ = 0, a1_ = 0, a2_ = 0, a3_ = 0;                    \
    _Pragma("unroll")                                                         \
    for (int j_ = 0; j_ < 32; j_ += 2) {                                      \
        const ulonglong2 q0_ = shv[j_], q1_ = shv[j_ + 1];                    \
        a0_ = fma2(q0_.x, eT[2 * j_ + 0], a0_);                               \
        a1_ = fma2(q0_.y, eT[2 * j_ + 1], a1_);                               \
        a2_ = fma2(q1_.x, eT[2 * j_ + 2], a2_);                               \
        a3_ = fma2(q1_.y, eT[2 * j_ + 3], a3_);                               \
    }                                                                         \
    const unsigned long long S_ = add2(add2(a0_, a1_), add2(a2_, a3_));       \
    const unsigned long long V_ = mul2(S_, ep_);                              \
    upk2(V_, vx, vy);                                                         \
    ulonglong2 st_;                                                           \
    st_.x = pk2(vx, vx);                                                      \
    st_.y = pk2(vy, vy);                                                      \
    *reinterpret_cast<ulonglong2*>(&sh[w][2 * l]) = st_;                      \
    asm volatile("" ::: "memory");                                            \
} while (0)

    // ---- prologue: steps 1..7 (chunk 0, buffer 0); L >= 1024 always ----
#pragma unroll
    for (int t = 1; t < 8; t++) CRF_STEP(sp[w][0][t]);

    // ---- main: full chunks c while steps 8c..8c+7 are all < L ----
    int c = 1;
    for (; 8 * (c + 1) <= L; c++) {
        const int buf = c & 1;
        // commit chunk c+1 (held in prf) into buf^1; prefetch chunk c+2
        float4* dst = reinterpret_cast<float4*>(sp[w][buf ^ 1]);
#pragma unroll
        for (int j = 0; j < 4; j++) dst[j * 32 + l] = prf[j];
        const int nc = min(c + 2, NCH - 1);
#pragma unroll
        for (int j = 0; j < 4; j++) prf[j] = p4[nc * 128 + j * 32 + l];
        asm volatile("" ::: "memory");

        // 8 branch-free steps, straight-line
#pragma unroll
        for (int j = 0; j < 8; j++) CRF_STEP(sp[w][buf][j]);
    }

    // ---- epilogue: remaining steps 8c .. L-1 (chunk c, already staged) ----
    {
        const int buf = c & 1;
        for (int t = 8 * c; t < L; t++) CRF_STEP(sp[w][buf][t & 7]);
    }
#undef CRF_STEP

    // ---- finalize: logZ = log(sum v) + ktot*ln2 - s12 ----
    float sumv = vx + vy;
#pragma unroll
    for (int o = 16; o > 0; o >>= 1) sumv += __shfl_xor_sync(FULL, sumv, o);
    if (l == 0) {
        float s12 = 0.f;
#pragma unroll
        for (int j = 0; j < NSEG; j++) s12 += s12p[b][j];
        out[b] = logf(sumv) + (float)ktot * 0.6931471805599453f - s12;
    }
}

extern "C" void kernel_launch(void* const* d_in, const int* in_sizes, int n_in,
                              void* d_out, int out_size) {
    const float* p     = (const float*)d_in[0];
    const int*   y     = (const int*)d_in[1];
    const int*   mask  = (const int*)d_in[2];
    const float* trans = (const float*)d_in[3];
    float* out = (float*)d_out;
    len_kernel<<<Bb, 256>>>(mask);
    score_kernel<<<Bb * NSEG, 256>>>(p, y, trans);
    crf_forward_kernel<<<Bb / 2, 64>>>(p, trans, out);
}

// round 15
// speedup vs baseline: 1.0527x; 1.0527x over previous
#include <cuda_runtime.h>
#include <cuda_bf16.h>

#define FULL 0xffffffffu

static __device__ __forceinline__ unsigned long long pk2(float lo, float hi) {
    unsigned long long r;
    asm("mov.b64 %0, {%1,%2};" : "=l"(r) : "f"(lo), "f"(hi));
    return r;
}
static __device__ __forceinline__ void upk2(unsigned long long v, float& lo, float& hi) {
    asm("mov.b64 {%0,%1}, %2;" : "=f"(lo), "=f"(hi) : "l"(v));
}
static __device__ __forceinline__ unsigned long long fma2(unsigned long long a,
                                                          unsigned long long b,
                                                          unsigned long long c) {
    unsigned long long d;
    asm("fma.rn.f32x2 %0,%1,%2,%3;" : "=l"(d) : "l"(a), "l"(b), "l"(c));
    return d;
}
static __device__ __forceinline__ unsigned long long add2(unsigned long long a,
                                                           unsigned long long b) {
    unsigned long long d;
    asm("add.rn.f32x2 %0,%1,%2;" : "=l"(d) : "l"(a), "l"(b));
    return d;
}
static __device__ __forceinline__ unsigned long long mul2(unsigned long long a,
                                                           unsigned long long b) {
    unsigned long long d;
    asm("mul.rn.f32x2 %0,%1,%2;" : "=l"(d) : "l"(a), "l"(b));
    return d;
}

static constexpr int Bb = 256;
static constexpr int Tt = 2048;
static constexpr int Dd = 64;
static constexpr int NSEG = 8;
static constexpr int SEGT = Tt / NSEG;

__device__ float s12p[Bb][NSEG];
__device__ int   Lg[Bb];

// ============================================================================
// Pass 1a: valid length per batch.
// ============================================================================
__global__ __launch_bounds__(256) void len_kernel(const int* __restrict__ mask) {
    const int b = blockIdx.x, tid = threadIdx.x, w = tid >> 5, l = tid & 31;
    __shared__ int red[8];
    const int4* m4 = reinterpret_cast<const int4*>(mask + (size_t)b * Tt);
    int4 a = m4[tid], c = m4[256 + tid];
    int s = a.x + a.y + a.z + a.w + c.x + c.y + c.z + c.w;
#pragma unroll
    for (int o = 16; o > 0; o >>= 1) s += __shfl_xor_sync(FULL, s, o);
    if (l == 0) red[w] = s;
    __syncthreads();
    if (tid == 0) {
        int tot = 0;
#pragma unroll
        for (int j = 0; j < 8; j++) tot += red[j];
        Lg[b] = Tt - tot;
    }
}

// ============================================================================
// Pass 1b: emission + transition score partial for one (batch, segment).
// ============================================================================
__global__ __launch_bounds__(256) void score_kernel(
    const float* __restrict__ p,
    const int*   __restrict__ y,
    const float* __restrict__ trans)
{
    const int blk = blockIdx.x;
    const int b = blk >> 3, seg = blk & (NSEG - 1);
    const int tid = threadIdx.x, w = tid >> 5, l = tid & 31;
    const int t0 = seg * SEGT;

    __shared__ short lab[SEGT + 1];
    __shared__ float red[8];

    const int2* yB = reinterpret_cast<const int2*>(y + (size_t)b * Tt * Dd);
#pragma unroll 4
    for (int i = w; i <= SEGT; i += 8) {
        int t = t0 + i;
        if (t < Tt) {
            int2 yv = yB[t * 32 + l];
            unsigned bx = __ballot_sync(FULL, yv.x != 0);
            unsigned by = __ballot_sync(FULL, yv.y != 0);
            if (l == 0)
                lab[i] = bx ? (short)(2 * (__ffs(bx) - 1))
                            : (short)(2 * (__ffs(by) - 1) + 1);
        }
    }
    __syncthreads();

    const int L = Lg[b];
    const int t = t0 + tid;
    const int lt = lab[tid];
    float acc = 0.f;
    if (t < L)     acc += __ldg(&p[(size_t)b * Tt * Dd + (size_t)t * Dd + lt]);
    if (t + 1 < L) acc += __ldg(&trans[lt * Dd + lab[tid + 1]]);

#pragma unroll
    for (int o = 16; o > 0; o >>= 1) acc += __shfl_xor_sync(FULL, acc, o);
    if (l == 0) red[w] = acc;
    __syncthreads();
    if (tid == 0) {
        float tot = 0.f;
#pragma unroll
        for (int j = 0; j < 8; j++) tot += red[j];
        s12p[b][seg] = tot;
    }
}

// ============================================================================
// Pass 2: forward recurrence. ONE WARP = TWO independent batches interleaved.
// The two recurrence chains share the warp's issue slots: batch B's fma/LDS
// stream fills batch A's latency windows — no synchronization of any kind.
// eT registers (expT columns) are shared between the batches.
// Per-batch structure identical to the R8 champion: rolled loop, chunked
// p staging, duplicated-state broadcast via LDS.128, linear domain with
// power-of-two renormalization (exponent of v[0] read from smem, 1 step
// stale). Commit of state/ktot is guarded by warp-uniform t<L predicates.
// ============================================================================
static constexpr int CH  = 8;
static constexpr int NCH = Tt / CH;

__global__ __launch_bounds__(32) void crf_forward_kernel(
    const float* __restrict__ p,       // [B,T,D]
    const float* __restrict__ trans,   // [D,D]
    float*       __restrict__ out)     // [B]
{
    const int l  = threadIdx.x;
    const int b0 = blockIdx.x * 2;
    const int b1 = b0 + 1;

    __shared__ __align__(16) unsigned long long sh0[Dd], sh1[Dd];  // {v,v} dup
    __shared__ __align__(16) float sp0[2][CH][Dd], sp1[2][CH][Dd]; // staged p

    const int L0 = Lg[b0];
    const int L1 = Lg[b1];
    const int Lmax = max(L0, L1);

    // expT: all 64 rows, cols (2l,2l+1) — shared by both batches
    unsigned long long eT[64];
#pragma unroll
    for (int j = 0; j < 64; j++) {
        float2 tv = reinterpret_cast<const float2*>(trans)[j * 32 + l];
        eT[j] = pk2(__expf(tv.x), __expf(tv.y));
    }

    const float4* p40 = reinterpret_cast<const float4*>(p + (size_t)b0 * Tt * Dd);
    const float4* p41 = reinterpret_cast<const float4*>(p + (size_t)b1 * Tt * Dd);

    // stage chunks 0,1 of both batches; prefetch chunk 2 (4 float4/lane each)
    float4 pr0[4], pr1[4];
#pragma unroll
    for (int j = 0; j < 4; j++) {
        reinterpret_cast<float4*>(sp0[0])[j * 32 + l] = p40[j * 32 + l];
        reinterpret_cast<float4*>(sp0[1])[j * 32 + l] = p40[128 + j * 32 + l];
        reinterpret_cast<float4*>(sp1[0])[j * 32 + l] = p41[j * 32 + l];
        reinterpret_cast<float4*>(sp1[1])[j * 32 + l] = p41[128 + j * 32 + l];
        pr0[j] = p40[256 + j * 32 + l];
        pr1[j] = p41[256 + j * 32 + l];
    }
    __syncwarp();

    // ---- t = 0 init (both batches) ----
    float2 pa = *reinterpret_cast<const float2*>(&sp0[0][0][2 * l]);
    float2 pb = *reinterpret_cast<const float2*>(&sp1[0][0][2 * l]);
    float vx0 = __expf(pa.x), vy0 = __expf(pa.y);
    float vx1 = __expf(pb.x), vy1 = __expf(pb.y);
    int kt0 = 0, kt1 = 0;
    {
        ulonglong2 s0, s1;
        s0.x = pk2(vx0, vx0); s0.y = pk2(vy0, vy0);
        s1.x = pk2(vx1, vx1); s1.y = pk2(vy1, vy1);
        *reinterpret_cast<ulonglong2*>(&sh0[2 * l]) = s0;
        *reinterpret_cast<ulonglong2*>(&sh1[2 * l]) = s1;
    }
    __syncwarp();

    const ulonglong2* sv0 = reinterpret_cast<const ulonglong2*>(sh0);
    const ulonglong2* sv1 = reinterpret_cast<const ulonglong2*>(sh1);

    for (int t = 1; t < Lmax; t++) {
        const int ch = t >> 3, tb = t & 7, cb = ch & 1;

        if (tb == 0) {  // chunk boundary: commit chunk ch+1, prefetch ch+2
            float4* d0 = reinterpret_cast<float4*>(sp0[cb ^ 1]);
            float4* d1 = reinterpret_cast<float4*>(sp1[cb ^ 1]);
#pragma unroll
            for (int j = 0; j < 4; j++) { d0[j * 32 + l] = pr0[j]; d1[j * 32 + l] = pr1[j]; }
            const int nc = min(ch + 2, NCH - 1);
#pragma unroll
            for (int j = 0; j < 4; j++) { pr0[j] = p40[nc * 128 + j * 32 + l]; pr1[j] = p41[nc * 128 + j * 32 + l]; }
            __syncwarp();
        }

        // emission + renorm for both (off critical path)
        float2 pt0 = *reinterpret_cast<const float2*>(&sp0[cb][tb][2 * l]);
        float2 pt1 = *reinterpret_cast<const float2*>(&sp1[cb][tb][2 * l]);
        unsigned e0 = *reinterpret_cast<const unsigned*>(&sh0[0]);
        unsigned e1 = *reinterpret_cast<const unsigned*>(&sh1[0]);
        int k0 = (int)((e0 >> 23) & 255) - 127;
        int k1 = (int)((e1 >> 23) & 255) - 127;
        float sc0 = __uint_as_float((unsigned)(127 - k0) << 23);
        float sc1 = __uint_as_float((unsigned)(127 - k1) << 23);
        unsigned long long ep0 = pk2(__expf(pt0.x) * sc0, __expf(pt0.y) * sc0);
        unsigned long long ep1 = pk2(__expf(pt1.x) * sc1, __expf(pt1.y) * sc1);

        // interleaved matvecs: 64 LDS.128 + 128 FFMA2, 8 accumulator chains
        unsigned long long a0 = 0, a1 = 0, a2 = 0, a3 = 0;
        unsigned long long c0 = 0, c1 = 0, c2 = 0, c3 = 0;
#pragma unroll
        for (int j = 0; j < 32; j += 2) {
            ulonglong2 qa0 = sv0[j + 0];
            ulonglong2 qb0 = sv1[j + 0];
            ulonglong2 qa1 = sv0[j + 1];
            ulonglong2 qb1 = sv1[j + 1];
            a0 = fma2(qa0.x, eT[2 * j + 0], a0);
            c0 = fma2(qb0.x, eT[2 * j + 0], c0);
            a1 = fma2(qa0.y, eT[2 * j + 1], a1);
            c1 = fma2(qb0.y, eT[2 * j + 1], c1);
            a2 = fma2(qa1.x, eT[2 * j + 2], a2);
            c2 = fma2(qb1.x, eT[2 * j + 2], c2);
            a3 = fma2(qa1.y, eT[2 * j + 3], a3);
            c3 = fma2(qb1.y, eT[2 * j + 3], c3);
        }
        unsigned long long S0 = add2(add2(a0, a1), add2(a2, a3));
        unsigned long long S1 = add2(add2(c0, c1), add2(c2, c3));
        unsigned long long V0 = mul2(S0, ep0);
        unsigned long long V1 = mul2(S1, ep1);

        // warp-uniform guarded commits (batch frozen past its length)
        if (t < L0) {
            kt0 += k0;
            upk2(V0, vx0, vy0);
            ulonglong2 s0;
            s0.x = pk2(vx0, vx0); s0.y = pk2(vy0, vy0);
            *reinterpret_cast<ulonglong2*>(&sh0[2 * l]) = s0;
        }
        if (t < L1) {
            kt1 += k1;
            upk2(V1, vx1, vy1);
            ulonglong2 s1;
            s1.x = pk2(vx1, vx1); s1.y = pk2(vy1, vy1);
            *reinterpret_cast<ulonglong2*>(&sh1[2 * l]) = s1;
        }
        asm volatile("" ::: "memory");
    }

    // ---- finalize both batches ----
    float s0 = vx0 + vy0;
    float s1 = vx1 + vy1;
#pragma unroll
    for (int o = 16; o > 0; o >>= 1) {
        s0 += __shfl_xor_sync(FULL, s0, o);
        s1 += __shfl_xor_sync(FULL, s1, o);
    }
    if (l == 0) {
        float t0 = 0.f, t1 = 0.f;
#pragma unroll
        for (int j = 0; j < NSEG; j++) { t0 += s12p[b0][j]; t1 += s12p[b1][j]; }
        out[b0] = logf(s0) + (float)kt0 * 0.6931471805599453f - t0;
        out[b1] = logf(s1) + (float)kt1 * 0.6931471805599453f - t1;
    }
}

extern "C" void kernel_launch(void* const* d_in, const int* in_sizes, int n_in,
                              void* d_out, int out_size) {
    const float* p     = (const float*)d_in[0];
    const int*   y     = (const int*)d_in[1];
    const int*   mask  = (const int*)d_in[2];
    const float* trans = (const float*)d_in[3];
    float* out = (float*)d_out;
    len_kernel<<<Bb, 256>>>(mask);
    score_kernel<<<Bb * NSEG, 256>>>(p, y, trans);
    crf_forward_kernel<<<Bb / 2, 32>>>(p, trans, out);
}